// round 11
// baseline (speedup 1.0000x reference)
#include <cuda_runtime.h>
#include <cuda_fp16.h>
#include <cstdint>
#include <cstddef>

#define T_    256
#define N_    256
#define C_    1408
#define CN1   16
#define KNN1  8
#define CN2   6
#define KNN2  3

// float32(sqrt(1408)) — divisor used by the reference (d / C**0.5)
#define SQC   37.52332607858744f

#define XSIZE 92274688   // 256*256*1408

// ---------------- static device scratch (allocation-free) ----------------
__device__ float g_d[(size_t)T_ * N_ * N_];        // 67 MB pairwise distances, layer 1
__device__ float g_sq[T_ * N_];
__device__ float g_dmax[T_];
__device__ float g_score[T_ * N_];
__device__ int   g_c1[T_ * CN1];
__device__ int   g_idx1[T_ * N_];
__device__ int   g_off1[T_ * (CN1 + 1)];
__device__ int   g_mlist1[T_ * N_];
__device__ float g_nw1[T_ * CN1];
__device__ float g_meta1[(size_t)T_ * CN1 * C_];   // 23 MB
__device__ int   g_idx2[T_ * CN1];
__device__ float g_meta2[(size_t)T_ * CN2 * C_];   // 8.7 MB

// ---------------- JAX threefry2x32, partitionable mode ----------------
__device__ __forceinline__ unsigned rotl32(unsigned x, int d) {
    return (x << d) | (x >> (32 - d));
}

__device__ float jax_uniform(unsigned keylo, unsigned e) {
    unsigned ks0 = 0u, ks1 = keylo, ks2 = keylo ^ 0x1BD11BDAu;
    unsigned x0 = ks0;          // counts_hi (=0) + ks0
    unsigned x1 = e + ks1;      // counts_lo + ks1
#define TF_R4(a,b,c,d)  do { \
    x0 += x1; x1 = rotl32(x1,(a)); x1 ^= x0; \
    x0 += x1; x1 = rotl32(x1,(b)); x1 ^= x0; \
    x0 += x1; x1 = rotl32(x1,(c)); x1 ^= x0; \
    x0 += x1; x1 = rotl32(x1,(d)); x1 ^= x0; } while (0)
    TF_R4(13,15,26,6);  x0 += ks1; x1 += ks2 + 1u;
    TF_R4(17,29,16,24); x0 += ks2; x1 += ks0 + 2u;
    TF_R4(13,15,26,6);  x0 += ks0; x1 += ks1 + 3u;
    TF_R4(17,29,16,24); x0 += ks1; x1 += ks2 + 4u;
    TF_R4(13,15,26,6);  x0 += ks2; x1 += ks0 + 5u;
#undef TF_R4
    unsigned bits = x0 ^ x1;
    return __uint_as_float((bits >> 9) | 0x3f800000u) - 1.0f;
}

// packed dual-FMA: each 32-bit lane is an independent IEEE fma.rn.f32
__device__ __forceinline__ void ffma2(unsigned long long& c,
                                      unsigned long long a,
                                      unsigned long long b) {
    asm("fma.rn.f32x2 %0, %1, %2, %0;" : "+l"(c) : "l"(a), "l"(b));
}

// ---------------- K0: squared row norms --------------------------------------------
__global__ void k_sq1(const float* __restrict__ x) {
    int t = blockIdx.x;
    int w = threadIdx.x >> 5, lane = threadIdx.x & 31;
    for (int r = w; r < N_; r += 8) {
        const float* row = x + ((size_t)t * N_ + r) * C_;
        float s = 0.f;
        for (int c = lane; c < C_; c += 32) {
            float v = row[c];
            s = __fadd_rn(s, __fmul_rn(v, v));
        }
        #pragma unroll
        for (int o = 16; o > 0; o >>= 1)
            s = __fadd_rn(s, __shfl_down_sync(0xffffffffu, s, o));
        if (lane == 0) g_sq[t * N_ + r] = s;
    }
}

// ---------------- K1: batched Gram GEMM + distance epilogue -------------------------
// 128x128 tile, 8x8 per thread, BK=8, packed f32x2 FMA (A duplicated in shared).
// Symmetry: m=0:(0,0), 1:(0,1)+mirror, 2:(1,1).  Each lane's op sequence is
// bit-identical to the scalar-FFMA version that passed with rel_err 0.0.
__global__ __launch_bounds__(256, 2) void k_gemm1(const float* __restrict__ x) {
    int t = blockIdx.y;
    int m = blockIdx.x;
    int bi = (m == 2) ? 1 : 0;
    int bj = (m == 0) ? 0 : 1;

    __shared__ float As2[8][256];   // A duplicated: As2[kk][2r]=As2[kk][2r+1]=A[r][kk]
    __shared__ float Bs[8][128];

    int tid = threadIdx.x;
    int lr = tid >> 1, lh = tid & 1;        // loader: row, k-half
    int tx = tid & 15, ty = tid >> 4;       // 16x16 compute grid

    const float* base = x + (size_t)t * N_ * C_;
    const float* Ap = base + (size_t)(bi * 128 + lr) * C_ + lh * 4;
    const float* Bp = base + (size_t)(bj * 128 + lr) * C_ + lh * 4;

    unsigned long long acc2[8][4];
    #pragma unroll
    for (int i = 0; i < 8; i++)
        #pragma unroll
        for (int jp = 0; jp < 4; jp++) acc2[i][jp] = 0ull;

    for (int k0 = 0; k0 < C_; k0 += 8) {
        float4 a = *(const float4*)(Ap + k0);
        float4 b = *(const float4*)(Bp + k0);
        __syncthreads();
        // duplicated A stores (float2 {v,v} -> STS.64)
        *(float2*)&As2[lh*4+0][2*lr] = make_float2(a.x, a.x);
        *(float2*)&As2[lh*4+1][2*lr] = make_float2(a.y, a.y);
        *(float2*)&As2[lh*4+2][2*lr] = make_float2(a.z, a.z);
        *(float2*)&As2[lh*4+3][2*lr] = make_float2(a.w, a.w);
        Bs[lh*4+0][lr] = b.x; Bs[lh*4+1][lr] = b.y; Bs[lh*4+2][lr] = b.z; Bs[lh*4+3][lr] = b.w;
        __syncthreads();
        #pragma unroll
        for (int kk = 0; kk < 8; kk++) {
            unsigned long long a2[8], b2[4];
            const unsigned long long* A64 = (const unsigned long long*)&As2[kk][ty * 16];
            const unsigned long long* B64 = (const unsigned long long*)&Bs[kk][tx * 8];
            #pragma unroll
            for (int i = 0; i < 8; i++) a2[i] = A64[i];
            #pragma unroll
            for (int jp = 0; jp < 4; jp++) b2[jp] = B64[jp];
            #pragma unroll
            for (int i = 0; i < 8; i++)
                #pragma unroll
                for (int jp = 0; jp < 4; jp++)
                    ffma2(acc2[i][jp], a2[i], b2[jp]);
        }
    }

    float sqi[8], sqj[8];
    #pragma unroll
    for (int i = 0; i < 8; i++) sqi[i] = g_sq[t * N_ + bi * 128 + ty * 8 + i];
    #pragma unroll
    for (int j = 0; j < 8; j++) sqj[j] = g_sq[t * N_ + bj * 128 + tx * 8 + j];

    float* D = g_d + (size_t)t * N_ * N_;
    #pragma unroll
    for (int i = 0; i < 8; i++) {
        int gi = bi * 128 + ty * 8 + i;
        #pragma unroll
        for (int jp = 0; jp < 4; jp++) {
            float2 av = *(float2*)&acc2[i][jp];
            #pragma unroll
            for (int h = 0; h < 2; h++) {
                int j = jp * 2 + h;
                int gj = bj * 128 + tx * 8 + j;
                float accv = (h == 0) ? av.x : av.y;
                float d2 = __fsub_rn(__fadd_rn(sqi[i], sqj[j]), __fmul_rn(2.0f, accv));
                float dd = __fdiv_rn(sqrtf(fmaxf(d2, 0.f)), SQC);
                D[(size_t)gi * N_ + gj] = dd;
                if (m == 1) D[(size_t)gj * N_ + gi] = dd;   // bit-exact mirror
            }
        }
    }
}

// ---------------- K2: fused density (8-NN) + noise + dist-to-higher + score --------
__global__ void k_densdist(void) {
    int t = blockIdx.x, i = threadIdx.x;
    const float* dc = g_d + (size_t)t * N_ * N_ + i;   // column i == row i (symmetric)
    __shared__ float sdens[256];
    __shared__ float red[256];

    float best[KNN1];
    #pragma unroll
    for (int k = 0; k < KNN1; k++) best[k] = 3.4e38f;
    float mx = 0.f;
    for (int j = 0; j < N_; j++) {
        float v = dc[(size_t)j << 8];
        mx = fmaxf(mx, v);
        if (v < best[KNN1 - 1]) {
            best[KNN1 - 1] = v;
            #pragma unroll
            for (int p = KNN1 - 1; p > 0; p--) {
                if (best[p] < best[p - 1]) { float tmp = best[p-1]; best[p-1] = best[p]; best[p] = tmp; }
            }
        }
    }
    float s = 0.f;
    #pragma unroll
    for (int k = 0; k < KNN1; k++) s = __fadd_rn(s, __fmul_rn(best[k], best[k]));
    float mean = __fdiv_rn(s, 8.0f);
    float di = __fadd_rn(expf(-mean), __fmul_rn(jax_uniform(1u, (unsigned)(t * N_ + i)), 1e-6f));
    sdens[i] = di;
    red[i] = mx;
    __syncthreads();
    for (int o = 128; o > 0; o >>= 1) {
        if (i < o) red[i] = fmaxf(red[i], red[i + o]);
        __syncthreads();
    }
    float dmax = red[0];

    float mmin = dmax;
    for (int j = 0; j < N_; j++) {
        float v = dc[(size_t)j << 8];
        if (sdens[j] > di && v < mmin) mmin = v;
    }
    g_score[t * N_ + i] = __fmul_rn(mmin, di);
}

// ---------------- K4: top-16 scores (descending, tie -> lowest index) --------------
__global__ void k_top16(void) {
    int t = blockIdx.x, lane = threadIdx.x;
    __shared__ float sc[256];
    for (int j = lane; j < N_; j += 32) sc[j] = g_score[t * N_ + j];
    __syncwarp();
    for (int p = 0; p < CN1; p++) {
        float bv = -1.f; int bi = N_;
        for (int j = lane; j < N_; j += 32) {
            float v = sc[j];
            if (v > bv) { bv = v; bi = j; }
        }
        #pragma unroll
        for (int o = 16; o > 0; o >>= 1) {
            float ov = __shfl_down_sync(0xffffffffu, bv, o);
            int   oi = __shfl_down_sync(0xffffffffu, bi, o);
            if (ov > bv || (ov == bv && oi < bi)) { bv = ov; bi = oi; }
        }
        bi = __shfl_sync(0xffffffffu, bi, 0);
        if (lane == 0) { g_c1[t * CN1 + p] = bi; sc[bi] = -2.f; }
        __syncwarp();
    }
}

// ---------------- K5: assign to nearest center (tie -> lowest slot), force centers --
__global__ void k_assign1(void) {
    int t = blockIdx.x, n = threadIdx.x;
    __shared__ int c[CN1];
    if (n < CN1) c[n] = g_c1[t * CN1 + n];
    __syncthreads();
    const float* D = g_d + (size_t)t * N_ * N_;
    float bv = 3.4e38f; int bk = 0;
    #pragma unroll
    for (int k = 0; k < CN1; k++) {
        float v = D[(size_t)c[k] * N_ + n];
        if (v < bv) { bv = v; bk = k; }
    }
    #pragma unroll
    for (int k = 0; k < CN1; k++) if (n == c[k]) bk = k;
    g_idx1[t * N_ + n] = bk;
}

// ---------------- K6: bucket members per cluster (n-ascending), counts, weights ----
__global__ void k_bucket1(void) {
    int t = blockIdx.x, tid = threadIdx.x;
    __shared__ int sidx[256];
    __shared__ int cnt[CN1];
    __shared__ int off[CN1 + 1];
    sidx[tid] = g_idx1[t * N_ + tid];
    if (tid < CN1) cnt[tid] = 0;
    __syncthreads();
    atomicAdd(&cnt[sidx[tid]], 1);
    __syncthreads();
    if (tid == 0) {
        int a = 0;
        for (int k = 0; k < CN1; k++) { off[k] = a; a += cnt[k]; }
        off[CN1] = a;
    }
    __syncthreads();
    int my = sidx[tid], r = 0;
    for (int mm = 0; mm < tid; mm++) if (sidx[mm] == my) r++;
    g_mlist1[t * N_ + off[my] + r] = tid;
    if (tid <= CN1) g_off1[t * (CN1 + 1) + tid] = off[tid];
    if (tid < CN1) {
        float w = __fadd_rn((float)cnt[tid], 1e-6f);
        g_nw1[t * CN1 + tid] = __fdiv_rn(1.0f, w);
    }
}

// ---------------- K7: merge tokens -> meta1 (deterministic member order) -----------
__global__ void k_merge1(const float* __restrict__ x) {
    int k = blockIdx.x, t = blockIdx.y;
    int o0 = g_off1[t * (CN1 + 1) + k];
    int o1 = g_off1[t * (CN1 + 1) + k + 1];
    float nw = g_nw1[t * CN1 + k];
    int c = threadIdx.x;                        // 352 threads, 4 channels each
    float a0 = 0.f, a1 = 0.f, a2 = 0.f, a3 = 0.f;
    for (int mm = o0; mm < o1; mm++) {
        int n = g_mlist1[t * N_ + mm];
        const float* row = x + ((size_t)t * N_ + n) * C_;
        a0 = __fadd_rn(a0, __fmul_rn(row[c],        nw));
        a1 = __fadd_rn(a1, __fmul_rn(row[c + 352],  nw));
        a2 = __fadd_rn(a2, __fmul_rn(row[c + 704],  nw));
        a3 = __fadd_rn(a3, __fmul_rn(row[c + 1056], nw));
    }
    float* o = g_meta1 + ((size_t)t * CN1 + k) * C_;
    o[c] = a0; o[c + 352] = a1; o[c + 704] = a2; o[c + 1056] = a3;
}

// ---------------- K8: fused layer-2 clustering + merge -> meta2, idx2 --------------
__global__ void k_l2(void) {
    int t = blockIdx.x, tid = threadIdx.x;
    int w = tid >> 5, lane = tid & 31;
    const float* M = g_meta1 + (size_t)t * CN1 * C_;

    __shared__ float ssq[CN1];
    __shared__ float sd[CN1 * CN1];
    __shared__ float sdens[CN1];
    __shared__ float sscore[CN1];
    __shared__ float sdmax;
    __shared__ int   sc2[CN2];
    __shared__ int   sidx2[CN1];
    __shared__ float snw[CN2];

    for (int r = w; r < CN1; r += 8) {
        const float* row = M + (size_t)r * C_;
        float s = 0.f;
        for (int c = lane; c < C_; c += 32) {
            float v = row[c];
            s = __fadd_rn(s, __fmul_rn(v, v));
        }
        #pragma unroll
        for (int o = 16; o > 0; o >>= 1)
            s = __fadd_rn(s, __shfl_down_sync(0xffffffffu, s, o));
        if (lane == 0) ssq[r] = s;
    }
    __syncthreads();

    {
        int i = tid >> 4, j = tid & 15;
        const float4* A = (const float4*)(M + (size_t)i * C_);
        const float4* B = (const float4*)(M + (size_t)j * C_);
        float acc = 0.f;
        for (int c = 0; c < C_ / 4; c++) {
            float4 a = A[c], b = B[c];
            acc = fmaf(a.x, b.x, acc);
            acc = fmaf(a.y, b.y, acc);
            acc = fmaf(a.z, b.z, acc);
            acc = fmaf(a.w, b.w, acc);
        }
        float d2 = __fsub_rn(__fadd_rn(ssq[i], ssq[j]), __fmul_rn(2.0f, acc));
        sd[tid] = __fdiv_rn(sqrtf(fmaxf(d2, 0.f)), SQC);
    }
    __syncthreads();

    if (tid < CN1) {
        float b0 = 3.4e38f, b1 = 3.4e38f, b2 = 3.4e38f;
        for (int j = 0; j < CN1; j++) {
            float v = sd[tid * CN1 + j];
            if (v < b2) {
                b2 = v;
                if (b2 < b1) { float x_ = b1; b1 = b2; b2 = x_; }
                if (b1 < b0) { float x_ = b0; b0 = b1; b1 = x_; }
            }
        }
        float s = __fadd_rn(__fadd_rn(__fmul_rn(b0, b0), __fmul_rn(b1, b1)), __fmul_rn(b2, b2));
        float mean = __fdiv_rn(s, 3.0f);
        sdens[tid] = __fadd_rn(expf(-mean),
                               __fmul_rn(jax_uniform(2u, (unsigned)(t * CN1 + tid)), 1e-6f));
    }
    __syncthreads();

    if (tid == 0) {
        float m = 0.f;
        for (int q = 0; q < CN1 * CN1; q++) m = fmaxf(m, sd[q]);
        sdmax = m;
    }
    __syncthreads();

    if (tid < CN1) {
        float di = sdens[tid];
        float m = sdmax;
        for (int j = 0; j < CN1; j++)
            if (sdens[j] > di) { float v = sd[tid * CN1 + j]; if (v < m) m = v; }
        sscore[tid] = __fmul_rn(m, di);
    }
    __syncthreads();

    if (tid == 0) {
        float tmp[CN1];
        for (int q = 0; q < CN1; q++) tmp[q] = sscore[q];
        for (int p = 0; p < CN2; p++) {
            float bv = -1.f; int bi = 0;
            for (int q = 0; q < CN1; q++) if (tmp[q] > bv) { bv = tmp[q]; bi = q; }
            sc2[p] = bi;
            tmp[bi] = -2.f;
        }
    }
    __syncthreads();

    if (tid < CN1) {
        float bv = 3.4e38f; int bk = 0;
        #pragma unroll
        for (int k = 0; k < CN2; k++) {
            float v = sd[sc2[k] * CN1 + tid];
            if (v < bv) { bv = v; bk = k; }
        }
        #pragma unroll
        for (int k = 0; k < CN2; k++) if (tid == sc2[k]) bk = k;
        sidx2[tid] = bk;
        g_idx2[t * CN1 + tid] = bk;
    }
    __syncthreads();

    if (tid == 0) {
        int cnt[CN2] = {0, 0, 0, 0, 0, 0};
        for (int n = 0; n < CN1; n++) cnt[sidx2[n]]++;
        for (int k = 0; k < CN2; k++)
            snw[k] = __fdiv_rn(1.0f, __fadd_rn((float)cnt[k], 1e-6f));
    }
    __syncthreads();

    float* O = g_meta2 + (size_t)t * CN2 * C_;
    for (int c = tid; c < C_; c += 256) {
        float acc[CN2] = {0.f, 0.f, 0.f, 0.f, 0.f, 0.f};
        for (int n = 0; n < CN1; n++) {
            float v = __fmul_rn(M[(size_t)n * C_ + c], snw[sidx2[n]]);
            #pragma unroll
            for (int k = 0; k < CN2; k++)
                acc[k] = __fadd_rn(acc[k], (sidx2[n] == k) ? v : 0.f);
        }
        #pragma unroll
        for (int k = 0; k < CN2; k++) O[(size_t)k * C_ + c] = acc[k];
    }
}

// ---------------- K9: group() — fp16 semantics, f32 STORAGE ------------------------
__global__ void k_group(const float* __restrict__ W, const float* __restrict__ bb,
                        float* __restrict__ out) {
    int t = blockIdx.x, tid = threadIdx.x;
    int w = tid >> 5, lane = tid & 31;
    const float* M2 = g_meta2 + (size_t)t * CN2 * C_;
    const float* M1 = g_meta1 + (size_t)t * CN1 * C_;

    __shared__ float  smean[CN2];
    __shared__ __half smodu[CN2];
    __shared__ int    srow[CN1 + CN2];
    __shared__ __half smod[CN1 + CN2];

    if (w < CN2) {
        const float* row = M2 + (size_t)w * C_;
        float s = 0.f;
        for (int c = lane; c < C_; c += 32)
            s = __fadd_rn(s, __half2float(__float2half_rn(row[c])));
        #pragma unroll
        for (int o = 16; o > 0; o >>= 1)
            s = __fadd_rn(s, __shfl_down_sync(0xffffffffu, s, o));
        if (lane == 0) {
            float mean = __fdiv_rn(s, (float)C_);
            smean[w] = __half2float(__float2half_rn(mean));
        }
    }
    __syncthreads();

    if (tid == 0) {
        float s[CN2];
        for (int i = 0; i < CN2; i++) {
            float a = 0.f;
            for (int j = 0; j < CN2; j++) a = fmaf(smean[j], W[i * CN2 + j], a);
            s[i] = __fadd_rn(a, bb[i]);
        }
        float m = s[0];
        for (int i = 1; i < CN2; i++) m = fmaxf(m, s[i]);
        float e[CN2], ss = 0.f;
        for (int i = 0; i < CN2; i++) {
            e[i] = expf(__fsub_rn(s[i], m));
            ss = __fadd_rn(ss, e[i]);
        }
        for (int i = 0; i < CN2; i++)
            smodu[i] = __float2half_rn(__fdiv_rn(e[i], ss));

        int idx[CN1];
        for (int n = 0; n < CN1; n++) idx[n] = g_idx2[t * CN1 + n];
        int p = 0;
        for (int v = 0; v < CN2; v++) {
            srow[p] = v; smod[p] = smodu[v]; p++;
            for (int n = 0; n < CN1; n++)
                if (idx[n] == v) { srow[p] = CN2 + n; smod[p] = smodu[v]; p++; }
        }
    }
    __syncthreads();

    float* ob = out + (size_t)t * (CN1 + CN2) * C_;
    for (int r = 0; r < CN1 + CN2; r++) {
        int sr = srow[r];
        __half md = smod[r];
        const float* src = (sr < CN2) ? (M2 + (size_t)sr * C_)
                                      : (M1 + (size_t)(sr - CN2) * C_);
        for (int c = tid; c < C_; c += 256) {
            __half h = __hmul(__float2half_rn(src[c]), md);  // exact fp16 semantics
            ob[(size_t)r * C_ + c] = __half2float(h);        // stored as f32
        }
    }
}

// ---------------- launch: bind inputs by EXACT element counts ----------------------
extern "C" void kernel_launch(void* const* d_in, const int* in_sizes, int n_in,
                              void* d_out, int out_size) {
    const float* x = nullptr;   // vis_embed: exactly 92,274,688 f32
    const float* W = nullptr;   // score_w:   36
    const float* b = nullptr;   // score_b:   6
    for (int i = 0; i < n_in; i++) {
        if (in_sizes[i] == XSIZE) x = (const float*)d_in[i];
        else if (in_sizes[i] == 36) W = (const float*)d_in[i];
        else if (in_sizes[i] == 6)  b = (const float*)d_in[i];
    }
    if (!x) {
        long long best = -1;
        for (int i = 0; i < n_in; i++)
            if (in_sizes[i] > best) { best = in_sizes[i]; x = (const float*)d_in[i]; }
    }
    if (!W) W = (const float*)d_in[n_in > 1 ? 1 : 0];
    if (!b) b = (const float*)d_in[n_in > 2 ? 2 : 0];

    float* out = (float*)d_out;   // fp16 values stored as f32

    k_sq1     <<<T_, 256>>>(x);
    k_gemm1   <<<dim3(3, T_), 256>>>(x);
    k_densdist<<<T_, 256>>>();
    k_top16   <<<T_, 32>>>();
    k_assign1 <<<T_, 256>>>();
    k_bucket1 <<<T_, 256>>>();
    k_merge1  <<<dim3(CN1, T_), 352>>>(x);
    k_l2      <<<T_, 256>>>();
    k_group   <<<T_, 256>>>(W, b, out);
}

// round 14
// speedup vs baseline: 1.1631x; 1.1631x over previous
#include <cuda_runtime.h>
#include <cuda_fp16.h>
#include <cstdint>
#include <cstddef>

#define T_    256
#define N_    256
#define C_    1408
#define CN1   16
#define KNN1  8
#define CN2   6
#define KNN2  3

// float32(sqrt(1408)) — divisor used by the reference (d / C**0.5)
#define SQC   37.52332607858744f

#define XSIZE 92274688   // 256*256*1408

// ---------------- static device scratch (allocation-free) ----------------
__device__ float g_d[(size_t)T_ * N_ * N_];        // 67 MB pairwise distances, layer 1
__device__ float g_sq[T_ * N_];
__device__ float g_score[T_ * N_];
__device__ int   g_c1[T_ * CN1];
__device__ int   g_idx1[T_ * N_];
__device__ int   g_off1[T_ * (CN1 + 1)];
__device__ int   g_mlist1[T_ * N_];
__device__ float g_nw1[T_ * CN1];
__device__ float g_meta1[(size_t)T_ * CN1 * C_];   // 23 MB
__device__ int   g_idx2[T_ * CN1];
__device__ float g_meta2[(size_t)T_ * CN2 * C_];   // 8.7 MB

// ---------------- JAX threefry2x32, partitionable mode ----------------
__device__ __forceinline__ unsigned rotl32(unsigned x, int d) {
    return (x << d) | (x >> (32 - d));
}

__device__ float jax_uniform(unsigned keylo, unsigned e) {
    unsigned ks0 = 0u, ks1 = keylo, ks2 = keylo ^ 0x1BD11BDAu;
    unsigned x0 = ks0;          // counts_hi (=0) + ks0
    unsigned x1 = e + ks1;      // counts_lo + ks1
#define TF_R4(a,b,c,d)  do { \
    x0 += x1; x1 = rotl32(x1,(a)); x1 ^= x0; \
    x0 += x1; x1 = rotl32(x1,(b)); x1 ^= x0; \
    x0 += x1; x1 = rotl32(x1,(c)); x1 ^= x0; \
    x0 += x1; x1 = rotl32(x1,(d)); x1 ^= x0; } while (0)
    TF_R4(13,15,26,6);  x0 += ks1; x1 += ks2 + 1u;
    TF_R4(17,29,16,24); x0 += ks2; x1 += ks0 + 2u;
    TF_R4(13,15,26,6);  x0 += ks0; x1 += ks1 + 3u;
    TF_R4(17,29,16,24); x0 += ks1; x1 += ks2 + 4u;
    TF_R4(13,15,26,6);  x0 += ks2; x1 += ks0 + 5u;
#undef TF_R4
    unsigned bits = x0 ^ x1;
    return __uint_as_float((bits >> 9) | 0x3f800000u) - 1.0f;
}

// packed dual-FMA: each 32-bit lane is an independent IEEE fma.rn.f32
__device__ __forceinline__ void ffma2(unsigned long long& c,
                                      unsigned long long a,
                                      unsigned long long b) {
    asm("fma.rn.f32x2 %0, %1, %2, %0;" : "+l"(c) : "l"(a), "l"(b));
}
// pack two floats into a 64-bit register pair
__device__ __forceinline__ unsigned long long pack2(float lo, float hi) {
    unsigned long long r;
    asm("mov.b64 %0, {%1, %2};" : "=l"(r) : "f"(lo), "f"(hi));
    return r;
}

// ---------------- K0: squared row norms --------------------------------------------
__global__ void k_sq1(const float* __restrict__ x) {
    int t = blockIdx.x;
    int w = threadIdx.x >> 5, lane = threadIdx.x & 31;
    for (int r = w; r < N_; r += 8) {
        const float* row = x + ((size_t)t * N_ + r) * C_;
        float s = 0.f;
        for (int c = lane; c < C_; c += 32) {
            float v = row[c];
            s = __fadd_rn(s, __fmul_rn(v, v));
        }
        #pragma unroll
        for (int o = 16; o > 0; o >>= 1)
            s = __fadd_rn(s, __shfl_down_sync(0xffffffffu, s, o));
        if (lane == 0) g_sq[t * N_ + r] = s;
    }
}

// ---------------- K1: batched Gram GEMM + distance epilogue -------------------------
// 128x128 tile, 8x8 per thread, BK=8.  Scalar shared layout + LDS.128 loads
// (identical to the 1374us baseline); FFMA2 via register pairing only:
//   B pairs = natural float4 register pairs; A duplicate = mov.b64 {v,v}.
// Per-lane IEEE op sequence identical to the scalar version -> bit-exact.
__global__ __launch_bounds__(256, 2) void k_gemm1(const float* __restrict__ x) {
    int t = blockIdx.y;
    int m = blockIdx.x;
    int bi = (m == 2) ? 1 : 0;
    int bj = (m == 0) ? 0 : 1;

    __shared__ float As[8][128];
    __shared__ float Bs[8][128];

    int tid = threadIdx.x;
    int lr = tid >> 1, lh = tid & 1;        // loader: row, k-half
    int tx = tid & 15, ty = tid >> 4;       // 16x16 compute grid

    const float* base = x + (size_t)t * N_ * C_;
    const float* Ap = base + (size_t)(bi * 128 + lr) * C_ + lh * 4;
    const float* Bp = base + (size_t)(bj * 128 + lr) * C_ + lh * 4;

    unsigned long long acc2[8][4];
    #pragma unroll
    for (int i = 0; i < 8; i++)
        #pragma unroll
        for (int jp = 0; jp < 4; jp++) acc2[i][jp] = 0ull;

    for (int k0 = 0; k0 < C_; k0 += 8) {
        float4 a = *(const float4*)(Ap + k0);
        float4 b = *(const float4*)(Bp + k0);
        __syncthreads();
        As[lh*4+0][lr] = a.x; As[lh*4+1][lr] = a.y; As[lh*4+2][lr] = a.z; As[lh*4+3][lr] = a.w;
        Bs[lh*4+0][lr] = b.x; Bs[lh*4+1][lr] = b.y; Bs[lh*4+2][lr] = b.z; Bs[lh*4+3][lr] = b.w;
        __syncthreads();
        #pragma unroll
        for (int kk = 0; kk < 8; kk++) {
            float4 a0 = *(const float4*)&As[kk][ty * 8];
            float4 a1 = *(const float4*)&As[kk][ty * 8 + 4];
            float4 b0 = *(const float4*)&Bs[kk][tx * 8];
            float4 b1 = *(const float4*)&Bs[kk][tx * 8 + 4];

            unsigned long long bp[4];
            bp[0] = pack2(b0.x, b0.y);
            bp[1] = pack2(b0.z, b0.w);
            bp[2] = pack2(b1.x, b1.y);
            bp[3] = pack2(b1.z, b1.w);

            float av[8];
            av[0] = a0.x; av[1] = a0.y; av[2] = a0.z; av[3] = a0.w;
            av[4] = a1.x; av[5] = a1.y; av[6] = a1.z; av[7] = a1.w;

            #pragma unroll
            for (int i = 0; i < 8; i++) {
                unsigned long long ad = pack2(av[i], av[i]);
                #pragma unroll
                for (int jp = 0; jp < 4; jp++)
                    ffma2(acc2[i][jp], ad, bp[jp]);
            }
        }
    }

    float sqi[8], sqj[8];
    #pragma unroll
    for (int i = 0; i < 8; i++) sqi[i] = g_sq[t * N_ + bi * 128 + ty * 8 + i];
    #pragma unroll
    for (int j = 0; j < 8; j++) sqj[j] = g_sq[t * N_ + bj * 128 + tx * 8 + j];

    float* D = g_d + (size_t)t * N_ * N_;
    #pragma unroll
    for (int i = 0; i < 8; i++) {
        int gi = bi * 128 + ty * 8 + i;
        #pragma unroll
        for (int jp = 0; jp < 4; jp++) {
            float lo = __uint_as_float((unsigned)(acc2[i][jp] & 0xffffffffull));
            float hi = __uint_as_float((unsigned)(acc2[i][jp] >> 32));
            #pragma unroll
            for (int h = 0; h < 2; h++) {
                int j = jp * 2 + h;
                int gj = bj * 128 + tx * 8 + j;
                float accv = (h == 0) ? lo : hi;
                float d2 = __fsub_rn(__fadd_rn(sqi[i], sqj[j]), __fmul_rn(2.0f, accv));
                float dd = __fdiv_rn(sqrtf(fmaxf(d2, 0.f)), SQC);
                D[(size_t)gi * N_ + gj] = dd;
                if (m == 1) D[(size_t)gj * N_ + gi] = dd;   // bit-exact mirror
            }
        }
    }
}

// ---------------- K2: fused density (8-NN) + noise + dist-to-higher + score --------
__global__ void k_densdist(void) {
    int t = blockIdx.x, i = threadIdx.x;
    const float* dc = g_d + (size_t)t * N_ * N_ + i;   // column i == row i (symmetric)
    __shared__ float sdens[256];
    __shared__ float red[256];

    float best[KNN1];
    #pragma unroll
    for (int k = 0; k < KNN1; k++) best[k] = 3.4e38f;
    float mx = 0.f;
    for (int j = 0; j < N_; j++) {
        float v = dc[(size_t)j << 8];
        mx = fmaxf(mx, v);
        if (v < best[KNN1 - 1]) {
            best[KNN1 - 1] = v;
            #pragma unroll
            for (int p = KNN1 - 1; p > 0; p--) {
                if (best[p] < best[p - 1]) { float tmp = best[p-1]; best[p-1] = best[p]; best[p] = tmp; }
            }
        }
    }
    float s = 0.f;
    #pragma unroll
    for (int k = 0; k < KNN1; k++) s = __fadd_rn(s, __fmul_rn(best[k], best[k]));
    float mean = __fdiv_rn(s, 8.0f);
    float di = __fadd_rn(expf(-mean), __fmul_rn(jax_uniform(1u, (unsigned)(t * N_ + i)), 1e-6f));
    sdens[i] = di;
    red[i] = mx;
    __syncthreads();
    for (int o = 128; o > 0; o >>= 1) {
        if (i < o) red[i] = fmaxf(red[i], red[i + o]);
        __syncthreads();
    }
    float dmax = red[0];

    float mmin = dmax;
    for (int j = 0; j < N_; j++) {
        float v = dc[(size_t)j << 8];
        if (sdens[j] > di && v < mmin) mmin = v;
    }
    g_score[t * N_ + i] = __fmul_rn(mmin, di);
}

// ---------------- K4: top-16 scores (descending, tie -> lowest index) --------------
__global__ void k_top16(void) {
    int t = blockIdx.x, lane = threadIdx.x;
    __shared__ float sc[256];
    for (int j = lane; j < N_; j += 32) sc[j] = g_score[t * N_ + j];
    __syncwarp();
    for (int p = 0; p < CN1; p++) {
        float bv = -1.f; int bi = N_;
        for (int j = lane; j < N_; j += 32) {
            float v = sc[j];
            if (v > bv) { bv = v; bi = j; }
        }
        #pragma unroll
        for (int o = 16; o > 0; o >>= 1) {
            float ov = __shfl_down_sync(0xffffffffu, bv, o);
            int   oi = __shfl_down_sync(0xffffffffu, bi, o);
            if (ov > bv || (ov == bv && oi < bi)) { bv = ov; bi = oi; }
        }
        bi = __shfl_sync(0xffffffffu, bi, 0);
        if (lane == 0) { g_c1[t * CN1 + p] = bi; sc[bi] = -2.f; }
        __syncwarp();
    }
}

// ---------------- K5: assign to nearest center (tie -> lowest slot), force centers --
__global__ void k_assign1(void) {
    int t = blockIdx.x, n = threadIdx.x;
    __shared__ int c[CN1];
    if (n < CN1) c[n] = g_c1[t * CN1 + n];
    __syncthreads();
    const float* D = g_d + (size_t)t * N_ * N_;
    float bv = 3.4e38f; int bk = 0;
    #pragma unroll
    for (int k = 0; k < CN1; k++) {
        float v = D[(size_t)c[k] * N_ + n];
        if (v < bv) { bv = v; bk = k; }
    }
    #pragma unroll
    for (int k = 0; k < CN1; k++) if (n == c[k]) bk = k;
    g_idx1[t * N_ + n] = bk;
}

// ---------------- K6: bucket members per cluster (n-ascending), counts, weights ----
__global__ void k_bucket1(void) {
    int t = blockIdx.x, tid = threadIdx.x;
    __shared__ int sidx[256];
    __shared__ int cnt[CN1];
    __shared__ int off[CN1 + 1];
    sidx[tid] = g_idx1[t * N_ + tid];
    if (tid < CN1) cnt[tid] = 0;
    __syncthreads();
    atomicAdd(&cnt[sidx[tid]], 1);
    __syncthreads();
    if (tid == 0) {
        int a = 0;
        for (int k = 0; k < CN1; k++) { off[k] = a; a += cnt[k]; }
        off[CN1] = a;
    }
    __syncthreads();
    int my = sidx[tid], r = 0;
    for (int mm = 0; mm < tid; mm++) if (sidx[mm] == my) r++;
    g_mlist1[t * N_ + off[my] + r] = tid;
    if (tid <= CN1) g_off1[t * (CN1 + 1) + tid] = off[tid];
    if (tid < CN1) {
        float w = __fadd_rn((float)cnt[tid], 1e-6f);
        g_nw1[t * CN1 + tid] = __fdiv_rn(1.0f, w);
    }
}

// ---------------- K7: merge tokens -> meta1 (deterministic member order) -----------
__global__ void k_merge1(const float* __restrict__ x) {
    int k = blockIdx.x, t = blockIdx.y;
    int o0 = g_off1[t * (CN1 + 1) + k];
    int o1 = g_off1[t * (CN1 + 1) + k + 1];
    float nw = g_nw1[t * CN1 + k];
    int c = threadIdx.x;                        // 352 threads, 4 channels each
    float a0 = 0.f, a1 = 0.f, a2 = 0.f, a3 = 0.f;
    for (int mm = o0; mm < o1; mm++) {
        int n = g_mlist1[t * N_ + mm];
        const float* row = x + ((size_t)t * N_ + n) * C_;
        a0 = __fadd_rn(a0, __fmul_rn(row[c],        nw));
        a1 = __fadd_rn(a1, __fmul_rn(row[c + 352],  nw));
        a2 = __fadd_rn(a2, __fmul_rn(row[c + 704],  nw));
        a3 = __fadd_rn(a3, __fmul_rn(row[c + 1056], nw));
    }
    float* o = g_meta1 + ((size_t)t * CN1 + k) * C_;
    o[c] = a0; o[c + 352] = a1; o[c + 704] = a2; o[c + 1056] = a3;
}

// ---------------- K8: fused layer-2 clustering + merge -> meta2, idx2 --------------
__global__ void k_l2(void) {
    int t = blockIdx.x, tid = threadIdx.x;
    int w = tid >> 5, lane = tid & 31;
    const float* M = g_meta1 + (size_t)t * CN1 * C_;

    __shared__ float ssq[CN1];
    __shared__ float sd[CN1 * CN1];
    __shared__ float sdens[CN1];
    __shared__ float sscore[CN1];
    __shared__ float sdmax;
    __shared__ int   sc2[CN2];
    __shared__ int   sidx2[CN1];
    __shared__ float snw[CN2];

    for (int r = w; r < CN1; r += 8) {
        const float* row = M + (size_t)r * C_;
        float s = 0.f;
        for (int c = lane; c < C_; c += 32) {
            float v = row[c];
            s = __fadd_rn(s, __fmul_rn(v, v));
        }
        #pragma unroll
        for (int o = 16; o > 0; o >>= 1)
            s = __fadd_rn(s, __shfl_down_sync(0xffffffffu, s, o));
        if (lane == 0) ssq[r] = s;
    }
    __syncthreads();

    {
        int i = tid >> 4, j = tid & 15;
        const float4* A = (const float4*)(M + (size_t)i * C_);
        const float4* B = (const float4*)(M + (size_t)j * C_);
        float acc = 0.f;
        for (int c = 0; c < C_ / 4; c++) {
            float4 a = A[c], b = B[c];
            acc = fmaf(a.x, b.x, acc);
            acc = fmaf(a.y, b.y, acc);
            acc = fmaf(a.z, b.z, acc);
            acc = fmaf(a.w, b.w, acc);
        }
        float d2 = __fsub_rn(__fadd_rn(ssq[i], ssq[j]), __fmul_rn(2.0f, acc));
        sd[tid] = __fdiv_rn(sqrtf(fmaxf(d2, 0.f)), SQC);
    }
    __syncthreads();

    if (tid < CN1) {
        float b0 = 3.4e38f, b1 = 3.4e38f, b2 = 3.4e38f;
        for (int j = 0; j < CN1; j++) {
            float v = sd[tid * CN1 + j];
            if (v < b2) {
                b2 = v;
                if (b2 < b1) { float x_ = b1; b1 = b2; b2 = x_; }
                if (b1 < b0) { float x_ = b0; b0 = b1; b1 = x_; }
            }
        }
        float s = __fadd_rn(__fadd_rn(__fmul_rn(b0, b0), __fmul_rn(b1, b1)), __fmul_rn(b2, b2));
        float mean = __fdiv_rn(s, 3.0f);
        sdens[tid] = __fadd_rn(expf(-mean),
                               __fmul_rn(jax_uniform(2u, (unsigned)(t * CN1 + tid)), 1e-6f));
    }
    __syncthreads();

    if (tid == 0) {
        float m = 0.f;
        for (int q = 0; q < CN1 * CN1; q++) m = fmaxf(m, sd[q]);
        sdmax = m;
    }
    __syncthreads();

    if (tid < CN1) {
        float di = sdens[tid];
        float m = sdmax;
        for (int j = 0; j < CN1; j++)
            if (sdens[j] > di) { float v = sd[tid * CN1 + j]; if (v < m) m = v; }
        sscore[tid] = __fmul_rn(m, di);
    }
    __syncthreads();

    if (tid == 0) {
        float tmp[CN1];
        for (int q = 0; q < CN1; q++) tmp[q] = sscore[q];
        for (int p = 0; p < CN2; p++) {
            float bv = -1.f; int bi = 0;
            for (int q = 0; q < CN1; q++) if (tmp[q] > bv) { bv = tmp[q]; bi = q; }
            sc2[p] = bi;
            tmp[bi] = -2.f;
        }
    }
    __syncthreads();

    if (tid < CN1) {
        float bv = 3.4e38f; int bk = 0;
        #pragma unroll
        for (int k = 0; k < CN2; k++) {
            float v = sd[sc2[k] * CN1 + tid];
            if (v < bv) { bv = v; bk = k; }
        }
        #pragma unroll
        for (int k = 0; k < CN2; k++) if (tid == sc2[k]) bk = k;
        sidx2[tid] = bk;
        g_idx2[t * CN1 + tid] = bk;
    }
    __syncthreads();

    if (tid == 0) {
        int cnt[CN2] = {0, 0, 0, 0, 0, 0};
        for (int n = 0; n < CN1; n++) cnt[sidx2[n]]++;
        for (int k = 0; k < CN2; k++)
            snw[k] = __fdiv_rn(1.0f, __fadd_rn((float)cnt[k], 1e-6f));
    }
    __syncthreads();

    float* O = g_meta2 + (size_t)t * CN2 * C_;
    for (int c = tid; c < C_; c += 256) {
        float acc[CN2] = {0.f, 0.f, 0.f, 0.f, 0.f, 0.f};
        for (int n = 0; n < CN1; n++) {
            float v = __fmul_rn(M[(size_t)n * C_ + c], snw[sidx2[n]]);
            #pragma unroll
            for (int k = 0; k < CN2; k++)
                acc[k] = __fadd_rn(acc[k], (sidx2[n] == k) ? v : 0.f);
        }
        #pragma unroll
        for (int k = 0; k < CN2; k++) O[(size_t)k * C_ + c] = acc[k];
    }
}

// ---------------- K9: group() — fp16 semantics, f32 STORAGE ------------------------
__global__ void k_group(const float* __restrict__ W, const float* __restrict__ bb,
                        float* __restrict__ out) {
    int t = blockIdx.x, tid = threadIdx.x;
    int w = tid >> 5, lane = tid & 31;
    const float* M2 = g_meta2 + (size_t)t * CN2 * C_;
    const float* M1 = g_meta1 + (size_t)t * CN1 * C_;

    __shared__ float  smean[CN2];
    __shared__ __half smodu[CN2];
    __shared__ int    srow[CN1 + CN2];
    __shared__ __half smod[CN1 + CN2];

    if (w < CN2) {
        const float* row = M2 + (size_t)w * C_;
        float s = 0.f;
        for (int c = lane; c < C_; c += 32)
            s = __fadd_rn(s, __half2float(__float2half_rn(row[c])));
        #pragma unroll
        for (int o = 16; o > 0; o >>= 1)
            s = __fadd_rn(s, __shfl_down_sync(0xffffffffu, s, o));
        if (lane == 0) {
            float mean = __fdiv_rn(s, (float)C_);
            smean[w] = __half2float(__float2half_rn(mean));
        }
    }
    __syncthreads();

    if (tid == 0) {
        float s[CN2];
        for (int i = 0; i < CN2; i++) {
            float a = 0.f;
            for (int j = 0; j < CN2; j++) a = fmaf(smean[j], W[i * CN2 + j], a);
            s[i] = __fadd_rn(a, bb[i]);
        }
        float m = s[0];
        for (int i = 1; i < CN2; i++) m = fmaxf(m, s[i]);
        float e[CN2], ss = 0.f;
        for (int i = 0; i < CN2; i++) {
            e[i] = expf(__fsub_rn(s[i], m));
            ss = __fadd_rn(ss, e[i]);
        }
        for (int i = 0; i < CN2; i++)
            smodu[i] = __float2half_rn(__fdiv_rn(e[i], ss));

        int idx[CN1];
        for (int n = 0; n < CN1; n++) idx[n] = g_idx2[t * CN1 + n];
        int p = 0;
        for (int v = 0; v < CN2; v++) {
            srow[p] = v; smod[p] = smodu[v]; p++;
            for (int n = 0; n < CN1; n++)
                if (idx[n] == v) { srow[p] = CN2 + n; smod[p] = smodu[v]; p++; }
        }
    }
    __syncthreads();

    float* ob = out + (size_t)t * (CN1 + CN2) * C_;
    for (int r = 0; r < CN1 + CN2; r++) {
        int sr = srow[r];
        __half md = smod[r];
        const float* src = (sr < CN2) ? (M2 + (size_t)sr * C_)
                                      : (M1 + (size_t)(sr - CN2) * C_);
        for (int c = tid; c < C_; c += 256) {
            __half h = __hmul(__float2half_rn(src[c]), md);  // exact fp16 semantics
            ob[(size_t)r * C_ + c] = __half2float(h);        // stored as f32
        }
    }
}

// ---------------- launch: bind inputs by EXACT element counts ----------------------
extern "C" void kernel_launch(void* const* d_in, const int* in_sizes, int n_in,
                              void* d_out, int out_size) {
    const float* x = nullptr;   // vis_embed: exactly 92,274,688 f32
    const float* W = nullptr;   // score_w:   36
    const float* b = nullptr;   // score_b:   6
    for (int i = 0; i < n_in; i++) {
        if (in_sizes[i] == XSIZE) x = (const float*)d_in[i];
        else if (in_sizes[i] == 36) W = (const float*)d_in[i];
        else if (in_sizes[i] == 6)  b = (const float*)d_in[i];
    }
    if (!x) {
        long long best = -1;
        for (int i = 0; i < n_in; i++)
            if (in_sizes[i] > best) { best = in_sizes[i]; x = (const float*)d_in[i]; }
    }
    if (!W) W = (const float*)d_in[n_in > 1 ? 1 : 0];
    if (!b) b = (const float*)d_in[n_in > 2 ? 2 : 0];

    float* out = (float*)d_out;   // fp16 values stored as f32

    k_sq1     <<<T_, 256>>>(x);
    k_gemm1   <<<dim3(3, T_), 256>>>(x);
    k_densdist<<<T_, 256>>>();
    k_top16   <<<T_, 32>>>();
    k_assign1 <<<T_, 256>>>();
    k_bucket1 <<<T_, 256>>>();
    k_merge1  <<<dim3(CN1, T_), 352>>>(x);
    k_l2      <<<T_, 256>>>();
    k_group   <<<T_, 256>>>(W, b, out);
}